// round 1
// baseline (speedup 1.0000x reference)
#include <cuda_runtime.h>

// Per-class accumulators in device globals (no allocation allowed).
__device__ double g_sum[3];
__device__ double g_cnt[3];

__global__ void zero_kernel() {
    if (threadIdx.x < 3) {
        g_sum[threadIdx.x] = 0.0;
        g_cnt[threadIdx.x] = 0.0;
    }
}

__device__ __forceinline__ void accum_pixel(float x0, float x1, float x2,
                                            int l1, int l2,
                                            float& s0, float& s1, float& s2,
                                            int& c0, int& c1, int& c2) {
    int lab = l1 + 2 * l2;
    float m = fmaxf(x0, fmaxf(x1, x2));
    float e0 = __expf(x0 - m);
    float e1 = __expf(x1 - m);
    float e2 = __expf(x2 - m);
    float S = e0 + e1 + e2;
    float esel = (lab == 0) ? e0 : ((lab == 1) ? e1 : e2);
    float p = __fdividef(esel, S);
    float err = -__logf(p + 1e-8f);
    if (lab == 0)      { s0 += err; c0++; }
    else if (lab == 1) { s1 += err; c1++; }
    else               { s2 += err; c2++; }
}

__global__ void __launch_bounds__(256)
reduce_kernel(const float4* __restrict__ p0,
              const float4* __restrict__ p1,
              const float4* __restrict__ p2,
              const int4* __restrict__ L1,
              const int4* __restrict__ L2,
              int n4) {
    float s0 = 0.f, s1 = 0.f, s2 = 0.f;
    int c0 = 0, c1 = 0, c2 = 0;

    for (int i = blockIdx.x * blockDim.x + threadIdx.x; i < n4;
         i += gridDim.x * blockDim.x) {
        float4 a = p0[i];
        float4 b = p1[i];
        float4 c = p2[i];
        int4 u = L1[i];
        int4 v = L2[i];
        accum_pixel(a.x, b.x, c.x, u.x, v.x, s0, s1, s2, c0, c1, c2);
        accum_pixel(a.y, b.y, c.y, u.y, v.y, s0, s1, s2, c0, c1, c2);
        accum_pixel(a.z, b.z, c.z, u.z, v.z, s0, s1, s2, c0, c1, c2);
        accum_pixel(a.w, b.w, c.w, u.w, v.w, s0, s1, s2, c0, c1, c2);
    }

    // warp reduce
    #pragma unroll
    for (int off = 16; off > 0; off >>= 1) {
        s0 += __shfl_down_sync(0xffffffffu, s0, off);
        s1 += __shfl_down_sync(0xffffffffu, s1, off);
        s2 += __shfl_down_sync(0xffffffffu, s2, off);
        c0 += __shfl_down_sync(0xffffffffu, c0, off);
        c1 += __shfl_down_sync(0xffffffffu, c1, off);
        c2 += __shfl_down_sync(0xffffffffu, c2, off);
    }

    __shared__ float sh_s[3][8];
    __shared__ int   sh_c[3][8];
    int wid = threadIdx.x >> 5;
    int lid = threadIdx.x & 31;
    if (lid == 0) {
        sh_s[0][wid] = s0; sh_s[1][wid] = s1; sh_s[2][wid] = s2;
        sh_c[0][wid] = c0; sh_c[1][wid] = c1; sh_c[2][wid] = c2;
    }
    __syncthreads();
    if (wid == 0) {
        int nw = (blockDim.x + 31) >> 5;
        float a0 = (lid < nw) ? sh_s[0][lid] : 0.f;
        float a1 = (lid < nw) ? sh_s[1][lid] : 0.f;
        float a2 = (lid < nw) ? sh_s[2][lid] : 0.f;
        int   b0 = (lid < nw) ? sh_c[0][lid] : 0;
        int   b1 = (lid < nw) ? sh_c[1][lid] : 0;
        int   b2 = (lid < nw) ? sh_c[2][lid] : 0;
        #pragma unroll
        for (int off = 4; off > 0; off >>= 1) {
            a0 += __shfl_down_sync(0xffffffffu, a0, off);
            a1 += __shfl_down_sync(0xffffffffu, a1, off);
            a2 += __shfl_down_sync(0xffffffffu, a2, off);
            b0 += __shfl_down_sync(0xffffffffu, b0, off);
            b1 += __shfl_down_sync(0xffffffffu, b1, off);
            b2 += __shfl_down_sync(0xffffffffu, b2, off);
        }
        if (lid == 0) {
            atomicAdd(&g_sum[0], (double)a0);
            atomicAdd(&g_sum[1], (double)a1);
            atomicAdd(&g_sum[2], (double)a2);
            atomicAdd(&g_cnt[0], (double)b0);
            atomicAdd(&g_cnt[1], (double)b1);
            atomicAdd(&g_cnt[2], (double)b2);
        }
    }
}

__global__ void finalize_kernel(const float* __restrict__ weight,
                                float* __restrict__ out) {
    double tot = 0.0, present = 0.0;
    #pragma unroll
    for (int c = 0; c < 3; c++) {
        if (g_cnt[c] > 0.0) {
            tot += (double)weight[c] * g_sum[c] / g_cnt[c];
            present += 1.0;
        }
    }
    out[0] = (present > 0.0) ? (float)(tot / present) : 0.0f;
}

extern "C" void kernel_launch(void* const* d_in, const int* in_sizes, int n_in,
                              void* d_out, int out_size) {
    const float* probas = (const float*)d_in[0];   // [1,3,D,H,W]
    const float* weight = (const float*)d_in[1];   // [3]
    const int*   labels = (const int*)d_in[2];     // [1,3,D,H,W] one-hot

    long long P = (long long)in_sizes[0] / 3;      // pixels per channel plane
    int n4 = (int)(P / 4);                         // P divisible by 4

    const float4* p0 = (const float4*)(probas);
    const float4* p1 = (const float4*)(probas + P);
    const float4* p2 = (const float4*)(probas + 2 * P);
    const int4*   L1 = (const int4*)(labels + P);       // one-hot channel 1
    const int4*   L2 = (const int4*)(labels + 2 * P);   // one-hot channel 2

    zero_kernel<<<1, 32>>>();

    int threads = 256;
    int blocks = 148 * 8;  // grid-stride; saturates DRAM
    if (blocks > (n4 + threads - 1) / threads)
        blocks = (n4 + threads - 1) / threads;
    reduce_kernel<<<blocks, threads>>>(p0, p1, p2, L1, L2, n4);

    finalize_kernel<<<1, 1>>>(weight, (float*)d_out);
}